// round 1
// baseline (speedup 1.0000x reference)
#include <cuda_runtime.h>

// Scalar accumulator in device global memory (no allocation allowed).
__device__ double g_accum;

__global__ void yolo_zero_kernel() {
    if (threadIdx.x == 0 && blockIdx.x == 0) g_accum = 0.0;
}

__device__ __forceinline__ float sigmoidf(float x) {
    return 1.0f / (1.0f + expf(-x));
}

__global__ __launch_bounds__(256) void yolo_loss_kernel(
    const float4* __restrict__ pred,   // (B, 3, 8) -> 6 float4 per b
    const float4* __restrict__ gtb,    // (B, 8, 4) -> 8 float4 per b
    const int4*  __restrict__ gtc,     // (B, 8)    -> 2 int4 per b
    int B)
{
    int b = blockIdx.x * blockDim.x + threadIdx.x;
    float local = 0.0f;

    if (b < B) {
        // ---- loads (all static-indexed after unroll; stays in registers) ----
        float4 p4[6];
#pragma unroll
        for (int i = 0; i < 6; i++) p4[i] = pred[(size_t)b * 6 + i];
        const float* pp = reinterpret_cast<const float*>(p4);

        float4 g4[8];
#pragma unroll
        for (int i = 0; i < 8; i++) g4[i] = gtb[(size_t)b * 8 + i];

        int4 c0 = gtc[(size_t)b * 2 + 0];
        int4 c1 = gtc[(size_t)b * 2 + 1];
        int cls[8] = {c0.x, c0.y, c0.z, c0.w, c1.x, c1.y, c1.z, c1.w};

        // ---- precompute GT corners / areas (shared across 3 anchors) ----
        float gx1[8], gx2[8], gy1[8], gy2[8], garea[8];
#pragma unroll
        for (int n = 0; n < 8; n++) {
            float gx = g4[n].x, gy = g4[n].y, gw = g4[n].z, gh = g4[n].w;
            gx1[n] = gx - gw * 0.5f;
            gx2[n] = gx + gw * 0.5f;
            gy1[n] = gy - gh * 0.5f;
            gy2[n] = gy + gh * 0.5f;
            garea[n] = (gx2[n] - gx1[n]) * (gy2[n] - gy1[n]);
        }

#pragma unroll
        for (int a = 0; a < 3; a++) {
            float px = sigmoidf(pp[a * 8 + 0]);
            float py = sigmoidf(pp[a * 8 + 1]);
            float pw = pp[a * 8 + 2];
            float ph = pp[a * 8 + 3];
            float pconf = sigmoidf(pp[a * 8 + 4]);
            float l0 = pp[a * 8 + 5], l1 = pp[a * 8 + 6], l2 = pp[a * 8 + 7];

            float px1 = px - pw * 0.5f, px2 = px + pw * 0.5f;
            float py1 = py - ph * 0.5f, py2 = py + ph * 0.5f;
            float parea = (px2 - px1) * (py2 - py1);

            // argmax over IoU; track winning box + class in registers
            float best = -__int_as_float(0x7f800000);  // -inf
            float mbx = 0.f, mby = 0.f, mbw = 0.f, mbh = 0.f;
            int bcls = 0;
#pragma unroll
            for (int n = 0; n < 8; n++) {
                float iw = fmaxf(fminf(px2, gx2[n]) - fmaxf(px1, gx1[n]), 0.0f);
                float ih = fmaxf(fminf(py2, gy2[n]) - fmaxf(py1, gy1[n]), 0.0f);
                float inter = iw * ih;
                float iou = inter / (parea + garea[n] - inter + 1e-6f);
                if (iou > best) {
                    best = iou;
                    mbx = g4[n].x; mby = g4[n].y; mbw = g4[n].z; mbh = g4[n].w;
                    bcls = cls[n];
                }
            }

            bool matched = best > 0.5f;

            // confidence BCE term (always present, branch selects sign side)
            float logp   = fmaxf(logf(pconf),     -100.0f);
            float log1mp = fmaxf(log1pf(-pconf),  -100.0f);
            local += matched ? -logp : -log1mp;

            if (matched) {
                float dx = px - mbx, dy = py - mby, dw = pw - mbw, dh = ph - mbh;
                float coord = dx * dx + dy * dy + dw * dw + dh * dh;

                // log-softmax NLL over 3 classes
                float m = fmaxf(l0, fmaxf(l1, l2));
                float lse = m + logf(expf(l0 - m) + expf(l1 - m) + expf(l2 - m));
                float lc = (bcls == 0) ? l0 : (bcls == 1) ? l1 : l2;
                float nll = lse - lc;

                local += 5.0f * coord + nll;
            }
        }
    }

    // ---- block reduction (fp32 partials, <=768 elements per block) ----
    __shared__ float sdata[256];
    sdata[threadIdx.x] = local;
    __syncthreads();
#pragma unroll
    for (int s = 128; s > 0; s >>= 1) {
        if (threadIdx.x < s) sdata[threadIdx.x] += sdata[threadIdx.x + s];
        __syncthreads();
    }
    if (threadIdx.x == 0) atomicAdd(&g_accum, (double)sdata[0]);
}

__global__ void yolo_finalize_kernel(float* __restrict__ out, int B) {
    if (threadIdx.x == 0 && blockIdx.x == 0) {
        out[0] = (float)(g_accum / (double)B);
    }
}

extern "C" void kernel_launch(void* const* d_in, const int* in_sizes, int n_in,
                              void* d_out, int out_size) {
    const float4* pred = (const float4*)d_in[0];   // predictions (B,3,8) f32
    const float4* gtb  = (const float4*)d_in[1];   // gt_boxes (B,8,4) f32
    const int4*   gtc  = (const int4*)d_in[2];     // gt_classes (B,8) i32
    float* out = (float*)d_out;

    int B = in_sizes[0] / 24;  // (B,3,8) floats

    yolo_zero_kernel<<<1, 32>>>();
    int threads = 256;
    int blocks = (B + threads - 1) / threads;
    yolo_loss_kernel<<<blocks, threads>>>(pred, gtb, gtc, B);
    yolo_finalize_kernel<<<1, 32>>>(out, B);
}